// round 4
// baseline (speedup 1.0000x reference)
#include <cuda_runtime.h>
#include <cstdint>

// Problem constants (fixed by the reference)
#define BATCH 4
#define CHAN  256
#define HH    192
#define WW    192
#define HW    (HH*WW)
#define MAXD  4
#define WIN   9
#define NDISP 81

// Tiling
#define TILE_X 32
#define TILE_Y 8
#define PX     8                 // pixels per thread along x
#define NTX    (TILE_X / PX)     // 4
#define SROWS  (TILE_Y + 2*MAXD) // 16
#define SCOLS  (TILE_X + 2*MAXD) // 40 -> 10 float4 per row
#define SVEC   10
#define SPITCH 44                // 44%32==12 -> conflict-free across sy pairs; 176B row, 16B aligned
#define FPITCH 36                // 36%32==4  -> conflict-free across ty pairs; 144B row, 16B aligned
#define CH     8
#define NROUNDS (CHAN / CH)      // 32
#define NTHREADS (NTX * TILE_Y * WIN)  // 4*8*9 = 288 = 9 full warps, one dy per warp

#define S_VECS (CH * SROWS * SVEC)        // 1280 float4 per stage
#define F_VECS (CH * TILE_Y * (TILE_X/4)) // 512 float4 per stage
#define S_ROLES 5                          // 4 full * 288 + 128
#define F_ROLES 2                          // 288 + 224

#define S_BUF_BYTES (CH * SROWS * SPITCH * 4)   // 22528
#define F_BUF_BYTES (CH * TILE_Y * FPITCH * 4)  // 9216

typedef unsigned long long u64;

__device__ __forceinline__ void cp_async16(uint32_t saddr, const float* gptr, bool full)
{
    int sz = full ? 16 : 0;   // src-size 0 -> 16B zero fill (halo)
    asm volatile("cp.async.cg.shared.global [%0], [%1], 16, %2;\n"
                 :: "r"(saddr), "l"(gptr), "r"(sz));
}

__device__ __forceinline__ u64 pk(float lo, float hi)
{
    u64 v;
    asm("mov.b64 %0, {%1, %2};" : "=l"(v) : "f"(lo), "f"(hi));
    return v;
}

__device__ __forceinline__ void ffma2(u64& acc, u64 a, u64 b)
{
    asm("fma.rn.f32x2 %0, %1, %2, %3;" : "=l"(acc) : "l"(a), "l"(b), "l"(acc));
}

__device__ __forceinline__ void unpk(u64 v, float& lo, float& hi)
{
    asm("mov.b64 {%0, %1}, %2;" : "=f"(lo), "=f"(hi) : "l"(v));
}

__global__ __launch_bounds__(NTHREADS, 2)
void corr_kernel(const float* __restrict__ F,
                 const float* __restrict__ S,
                 float* __restrict__ out)
{
    __shared__ float sS[2][CH][SROWS][SPITCH];
    __shared__ float sF[2][CH][TILE_Y][FPITCH];

    const int tx = threadIdx.x;            // 0..3
    const int ty = threadIdx.y;            // 0..7
    const int g  = threadIdx.z;            // 0..8 (dy) == warp id
    const int tid = tx + NTX * ty + NTX * TILE_Y * g;

    const int tileX = blockIdx.x * TILE_X;
    const int tileY = blockIdx.y * TILE_Y;
    const int b     = blockIdx.z;

    const float* Fb = F + (size_t)b * CHAN * HW;
    const float* Sb = S + (size_t)b * CHAN * HW;

    // ---------------- precompute load roles ----------------
    const float* s_ptr[S_ROLES];
    uint32_t     s_smem[S_ROLES];
    bool         s_pred[S_ROLES];
#pragma unroll
    for (int k = 0; k < S_ROLES; k++) {
        int v   = tid + k * NTHREADS;
        if (v >= S_VECS) v = 0;            // inactive role; predicated off at issue
        int ch  = v / (SROWS * SVEC);
        int rem = v - ch * (SROWS * SVEC);
        int row = rem / SVEC;
        int c4  = rem - row * SVEC;
        int gy  = tileY + row - MAXD;
        int gx  = tileX + c4 * 4 - MAXD;
        bool inb = (gy >= 0) && (gy < HH) && (gx >= 0) && (gx + 4 <= WW);
        s_pred[k] = inb;
        s_ptr[k]  = Sb + (size_t)ch * HW + (inb ? (gy * WW + gx) : 0);
        s_smem[k] = (uint32_t)__cvta_generic_to_shared(&sS[0][ch][row][c4 * 4]);
    }
    const float* f_ptr[F_ROLES];
    uint32_t     f_smem[F_ROLES];
#pragma unroll
    for (int k = 0; k < F_ROLES; k++) {
        int v   = tid + k * NTHREADS;
        if (v >= F_VECS) v = 0;
        int ch  = v >> 6;                  // / 64  (8 float4 per row * 8 rows)
        int rem = v & 63;
        int row = rem >> 3;
        int c4  = rem & 7;
        f_ptr[k]  = Fb + (size_t)ch * HW + (tileY + row) * WW + tileX + c4 * 4;
        f_smem[k] = (uint32_t)__cvta_generic_to_shared(&sF[0][ch][row][c4 * 4]);
    }

    auto issue = [&](int r) {
        uint32_t sOff = (r & 1) ? (uint32_t)S_BUF_BYTES : 0u;
        uint32_t fOff = (r & 1) ? (uint32_t)F_BUF_BYTES : 0u;
        size_t   cOff = (size_t)r * CH * HW;
#pragma unroll
        for (int k = 0; k < S_ROLES; k++) {
            if (k < S_ROLES - 1 || tid < (S_VECS - (S_ROLES - 1) * NTHREADS)) {
                cp_async16(s_smem[k] + sOff, s_ptr[k] + cOff, s_pred[k]);
            }
        }
#pragma unroll
        for (int k = 0; k < F_ROLES; k++) {
            if (k < F_ROLES - 1 || tid < (F_VECS - (F_ROLES - 1) * NTHREADS)) {
                cp_async16(f_smem[k] + fOff, f_ptr[k] + cOff, true);
            }
        }
        asm volatile("cp.async.commit_group;\n" ::: "memory");
    };

    // accumulators: 4 pixel-pairs x 9 dx, packed f32x2
    u64 A[4][WIN];
#pragma unroll
    for (int q = 0; q < 4; q++)
#pragma unroll
        for (int d = 0; d < WIN; d++) A[q][d] = 0ull;

    const int x0 = PX * tx;      // 0,8,16,24
    const int sy = ty + g;       // 0..15

    issue(0);

    for (int r = 0; r < NROUNDS; r++) {
        asm volatile("cp.async.wait_group 0;\n" ::: "memory");
        __syncthreads();
        if (r + 1 < NROUNDS) issue(r + 1);

        const int bb = r & 1;
#pragma unroll
        for (int ch = 0; ch < CH; ch++) {
            const float* fr = &sF[bb][ch][ty][x0];
            float4 f0 = *(const float4*)fr;
            float4 f1 = *(const float4*)(fr + 4);
            u64 fp[4] = { pk(f0.x, f0.y), pk(f0.z, f0.w),
                          pk(f1.x, f1.y), pk(f1.z, f1.w) };

            const float* wr = &sS[bb][ch][sy][x0];
            float4 w0 = *(const float4*)wr;
            float4 w1 = *(const float4*)(wr + 4);
            float4 w2 = *(const float4*)(wr + 8);
            float4 w3 = *(const float4*)(wr + 12);
            float w[16] = { w0.x, w0.y, w0.z, w0.w,
                            w1.x, w1.y, w1.z, w1.w,
                            w2.x, w2.y, w2.z, w2.w,
                            w3.x, w3.y, w3.z, w3.w };

            // iterate by window-pair index j so only one wp pack is live
#pragma unroll
            for (int j = 0; j < 15; j++) {
                u64 wj = pk(w[j], w[j + 1]);
#pragma unroll
                for (int q = 0; q < 4; q++) {
                    const int d = j - 2 * q;
                    if (d >= 0 && d < WIN) {
                        ffma2(A[q][d], fp[q], wj);
                    }
                }
            }
        }
    }

    // ---------------- store: scale by 1/C ----------------
    const float inv = 1.0f / (float)CHAN;
    const int y  = tileY + ty;
    const int gx = tileX + x0;
#pragma unroll
    for (int d = 0; d < WIN; d++) {
        int disp = g * WIN + d;
        float p0, p1, p2, p3, p4, p5, p6, p7;
        unpk(A[0][d], p0, p1);
        unpk(A[1][d], p2, p3);
        unpk(A[2][d], p4, p5);
        unpk(A[3][d], p6, p7);
        float4 v0 = { p0 * inv, p1 * inv, p2 * inv, p3 * inv };
        float4 v1 = { p4 * inv, p5 * inv, p6 * inv, p7 * inv };
        float* o = &out[((size_t)(b * NDISP + disp) * HH + y) * WW + gx];
        *(float4*)o       = v0;
        *(float4*)(o + 4) = v1;
    }
}

extern "C" void kernel_launch(void* const* d_in, const int* in_sizes, int n_in,
                              void* d_out, int out_size)
{
    const float* tensorFirst  = (const float*)d_in[0];
    const float* tensorSecond = (const float*)d_in[1];
    float* out = (float*)d_out;

    dim3 grid(WW / TILE_X, HH / TILE_Y, BATCH);   // 6 x 24 x 4 = 576
    dim3 block(NTX, TILE_Y, WIN);                 // 4 x 8 x 9 = 288
    corr_kernel<<<grid, block>>>(tensorFirst, tensorSecond, out);
}

// round 5
// speedup vs baseline: 1.0076x; 1.0076x over previous
#include <cuda_runtime.h>
#include <cstdint>

// Problem constants (fixed by the reference)
#define BATCH 4
#define CHAN  256
#define HH    192
#define WW    192
#define HW    (HH*WW)
#define MAXD  4
#define WIN   9
#define NDISP 81

// Tiling
#define TILE_X 32
#define TILE_Y 8
#define PX     8                 // pixels per thread along x
#define NTX    (TILE_X / PX)     // 4
#define SROWS  (TILE_Y + 2*MAXD) // 16
#define SVEC   10                // float4s per S row (40 cols)
#define SPITCH 44                // 176B row: conflict-free, 16B aligned
#define FPITCH 36                // 144B row: conflict-free, 16B aligned
#define CH     8
#define NROUNDS (CHAN / CH)      // 32
#define NTHREADS (NTX * TILE_Y * WIN)  // 288 = 9 warps, one dy per warp

#define S_VECS (CH * SROWS * SVEC)        // 1280 float4 per stage
#define F_VECS (CH * TILE_Y * (TILE_X/4)) // 512 float4 per stage
#define S_ROLES 5
#define F_ROLES 2

#define S_BUF_BYTES (CH * SROWS * SPITCH * 4)   // 22528
#define F_BUF_BYTES (CH * TILE_Y * FPITCH * 4)  // 9216

typedef unsigned long long u64;

__device__ __forceinline__ void cp_async16(uint32_t saddr, const float* gptr, bool full)
{
    int sz = full ? 16 : 0;   // src-size 0 -> 16B zero fill (halo)
    asm volatile("cp.async.cg.shared.global [%0], [%1], 16, %2;\n"
                 :: "r"(saddr), "l"(gptr), "r"(sz));
}

__device__ __forceinline__ u64 pk(float lo, float hi)
{
    u64 v;
    asm("mov.b64 %0, {%1, %2};" : "=l"(v) : "f"(lo), "f"(hi));
    return v;
}

__device__ __forceinline__ float lo32(u64 v)
{
    float f;
    asm("{ .reg .b32 t; mov.b64 {%0, t}, %1; }" : "=f"(f) : "l"(v));
    return f;
}

__device__ __forceinline__ float hi32(u64 v)
{
    float f;
    asm("{ .reg .b32 t; mov.b64 {t, %0}, %1; }" : "=f"(f) : "l"(v));
    return f;
}

__device__ __forceinline__ void ffma2(u64& acc, u64 a, u64 b)
{
    asm("fma.rn.f32x2 %0, %1, %2, %3;" : "=l"(acc) : "l"(a), "l"(b), "l"(acc));
}

__device__ __forceinline__ void unpk(u64 v, float& lo, float& hi)
{
    asm("mov.b64 {%0, %1}, %2;" : "=f"(lo), "=f"(hi) : "l"(v));
}

__global__ __launch_bounds__(NTHREADS, 2)
void corr_kernel(const float* __restrict__ F,
                 const float* __restrict__ S,
                 float* __restrict__ out)
{
    __shared__ __align__(16) float sS[2][CH][SROWS][SPITCH];
    __shared__ __align__(16) float sF[2][CH][TILE_Y][FPITCH];

    const int tx = threadIdx.x;            // 0..3
    const int ty = threadIdx.y;            // 0..7
    const int g  = threadIdx.z;            // 0..8 (dy) == warp id
    const int tid = tx + NTX * ty + NTX * TILE_Y * g;

    const int tileX = blockIdx.x * TILE_X;
    const int tileY = blockIdx.y * TILE_Y;
    const int b     = blockIdx.z;

    const float* Fb = F + (size_t)b * CHAN * HW;
    const float* Sb = S + (size_t)b * CHAN * HW;

    // ---------------- precompute load roles ----------------
    const float* s_ptr[S_ROLES];
    uint32_t     s_smem[S_ROLES];
    bool         s_pred[S_ROLES];
#pragma unroll
    for (int k = 0; k < S_ROLES; k++) {
        int v   = tid + k * NTHREADS;
        if (v >= S_VECS) v = 0;
        int ch  = v / (SROWS * SVEC);
        int rem = v - ch * (SROWS * SVEC);
        int row = rem / SVEC;
        int c4  = rem - row * SVEC;
        int gy  = tileY + row - MAXD;
        int gx  = tileX + c4 * 4 - MAXD;
        bool inb = (gy >= 0) && (gy < HH) && (gx >= 0) && (gx + 4 <= WW);
        s_pred[k] = inb;
        s_ptr[k]  = Sb + (size_t)ch * HW + (inb ? (gy * WW + gx) : 0);
        s_smem[k] = (uint32_t)__cvta_generic_to_shared(&sS[0][ch][row][c4 * 4]);
    }
    const float* f_ptr[F_ROLES];
    uint32_t     f_smem[F_ROLES];
#pragma unroll
    for (int k = 0; k < F_ROLES; k++) {
        int v   = tid + k * NTHREADS;
        if (v >= F_VECS) v = 0;
        int ch  = v >> 6;
        int rem = v & 63;
        int row = rem >> 3;
        int c4  = rem & 7;
        f_ptr[k]  = Fb + (size_t)ch * HW + (tileY + row) * WW + tileX + c4 * 4;
        f_smem[k] = (uint32_t)__cvta_generic_to_shared(&sF[0][ch][row][c4 * 4]);
    }

    auto issue = [&](int r) {
        uint32_t sOff = (r & 1) ? (uint32_t)S_BUF_BYTES : 0u;
        uint32_t fOff = (r & 1) ? (uint32_t)F_BUF_BYTES : 0u;
        size_t   cOff = (size_t)r * CH * HW;
#pragma unroll
        for (int k = 0; k < S_ROLES; k++) {
            if (k < S_ROLES - 1 || tid < (S_VECS - (S_ROLES - 1) * NTHREADS)) {
                cp_async16(s_smem[k] + sOff, s_ptr[k] + cOff, s_pred[k]);
            }
        }
#pragma unroll
        for (int k = 0; k < F_ROLES; k++) {
            if (k < F_ROLES - 1 || tid < (F_VECS - (F_ROLES - 1) * NTHREADS)) {
                cp_async16(f_smem[k] + fOff, f_ptr[k] + cOff, true);
            }
        }
        asm volatile("cp.async.commit_group;\n" ::: "memory");
    };

    // accumulators: 4 pixel-pairs x 9 dx, packed f32x2
    u64 A[4][WIN];
#pragma unroll
    for (int q = 0; q < 4; q++)
#pragma unroll
        for (int d = 0; d < WIN; d++) A[q][d] = 0ull;

    const int x0 = PX * tx;      // 0,8,16,24
    const int sy = ty + g;       // 0..15

    issue(0);

    for (int r = 0; r < NROUNDS; r++) {
        asm volatile("cp.async.wait_group 0;\n" ::: "memory");
        __syncthreads();
        if (r + 1 < NROUNDS) issue(r + 1);

        const int bb = r & 1;
#pragma unroll
        for (int ch = 0; ch < CH; ch++) {
            // F pixels: 8 floats = 4 aligned f32x2 pairs, loaded directly as u64
            const ulonglong2* fv = (const ulonglong2*)&sF[bb][ch][ty][x0];
            ulonglong2 fA = fv[0];
            ulonglong2 fB = fv[1];
            u64 fp[4] = { fA.x, fA.y, fB.x, fB.y };

            // S window: 16 floats = 8 aligned f32x2 pairs
            const ulonglong2* wv = (const ulonglong2*)&sS[bb][ch][sy][x0];
            ulonglong2 w01 = wv[0];
            ulonglong2 w23 = wv[1];
            ulonglong2 w45 = wv[2];
            ulonglong2 w67 = wv[3];
            u64 wp[8] = { w01.x, w01.y, w23.x, w23.y,
                          w45.x, w45.y, w67.x, w67.y };

            // even-start pairs (s = 2q+d even): operands already aligned, zero MOVs
#pragma unroll
            for (int q = 0; q < 4; q++) {
#pragma unroll
                for (int d = 0; d < WIN; d += 2) {
                    ffma2(A[q][d], fp[q], wp[q + d / 2]);
                }
            }

            // odd-start pairs: 7 transient repacks, consumed immediately
#pragma unroll
            for (int i = 0; i < 7; i++) {
                u64 wo = pk(hi32(wp[i]), lo32(wp[i + 1]));
#pragma unroll
                for (int q = 0; q < 4; q++) {
                    const int d = 2 * i + 1 - 2 * q;
                    if (d >= 0 && d < WIN) {
                        ffma2(A[q][d], fp[q], wo);
                    }
                }
            }
        }
    }

    // ---------------- store: scale by 1/C ----------------
    const float inv = 1.0f / (float)CHAN;
    const int y  = tileY + ty;
    const int gx = tileX + x0;
#pragma unroll
    for (int d = 0; d < WIN; d++) {
        int disp = g * WIN + d;
        float p0, p1, p2, p3, p4, p5, p6, p7;
        unpk(A[0][d], p0, p1);
        unpk(A[1][d], p2, p3);
        unpk(A[2][d], p4, p5);
        unpk(A[3][d], p6, p7);
        float4 v0 = { p0 * inv, p1 * inv, p2 * inv, p3 * inv };
        float4 v1 = { p4 * inv, p5 * inv, p6 * inv, p7 * inv };
        float* o = &out[((size_t)(b * NDISP + disp) * HH + y) * WW + gx];
        *(float4*)o       = v0;
        *(float4*)(o + 4) = v1;
    }
}

extern "C" void kernel_launch(void* const* d_in, const int* in_sizes, int n_in,
                              void* d_out, int out_size)
{
    const float* tensorFirst  = (const float*)d_in[0];
    const float* tensorSecond = (const float*)d_in[1];
    float* out = (float*)d_out;

    dim3 grid(WW / TILE_X, HH / TILE_Y, BATCH);   // 6 x 24 x 4 = 576
    dim3 block(NTX, TILE_Y, WIN);                 // 4 x 8 x 9 = 288
    corr_kernel<<<grid, block>>>(tensorFirst, tensorSecond, out);
}

// round 6
// speedup vs baseline: 1.0143x; 1.0067x over previous
#include <cuda_runtime.h>
#include <cstdint>

// Problem constants (fixed by the reference)
#define BATCH 4
#define CHAN  256
#define HH    192
#define WW    192
#define HW    (HH*WW)
#define MAXD  4
#define WIN   9
#define NDISP 81

// Tiling
#define TILE_X 32
#define TILE_Y 8
#define PX     8
#define NTX    (TILE_X / PX)     // 4
#define SROWS  (TILE_Y + 2*MAXD) // 16
#define SVEC   10                // float4s per S row (40 cols)
#define SPITCH 44                // 176B row: conflict-free, 16B aligned
#define FPITCH 36                // 144B row: conflict-free, 16B aligned
#define CH     8
#define NROUNDS (CHAN / CH)      // 32
#define NTHREADS (NTX * TILE_Y * WIN)  // 288 = 9 warps, one dy per warp

#define S_VECS (CH * SROWS * SVEC)        // 1280 float4 per stage
#define F_VECS (CH * TILE_Y * (TILE_X/4)) // 512 float4 per stage
#define S_ROLES 5
#define F_ROLES 2

#define S_BUF_BYTES (CH * SROWS * SPITCH * 4)   // 22528
#define F_BUF_BYTES (CH * TILE_Y * FPITCH * 4)  // 9216

typedef unsigned long long u64;

__device__ __forceinline__ void cp_async16(uint32_t saddr, const float* gptr, bool full)
{
    int sz = full ? 16 : 0;   // src-size 0 -> 16B zero fill (halo)
    asm volatile("cp.async.cg.shared.global [%0], [%1], 16, %2;\n"
                 :: "r"(saddr), "l"(gptr), "r"(sz));
}

// pack two scalar floats into a b64 pair; when lo/hi already sit in adjacent
// aligned registers (float4 members), ptxas coalesces this to zero MOVs.
__device__ __forceinline__ u64 pk(float lo, float hi)
{
    u64 v;
    asm("mov.b64 %0, {%1, %2};" : "=l"(v) : "f"(lo), "f"(hi));
    return v;
}

// single-instruction packed FMA on prebuilt b64 operands
__device__ __forceinline__ void ffma2(u64& acc, u64 a, u64 b)
{
    asm("fma.rn.f32x2 %0, %1, %2, %3;" : "=l"(acc) : "l"(a), "l"(b), "l"(acc));
}

__device__ __forceinline__ void unpk(u64 v, float& lo, float& hi)
{
    asm("mov.b64 {%0, %1}, %2;" : "=f"(lo), "=f"(hi) : "l"(v));
}

__global__ __launch_bounds__(NTHREADS, 2)
void corr_kernel(const float* __restrict__ F,
                 const float* __restrict__ S,
                 float* __restrict__ out)
{
    __shared__ __align__(16) float sS[2][CH][SROWS][SPITCH];
    __shared__ __align__(16) float sF[2][CH][TILE_Y][FPITCH];

    const int tx = threadIdx.x;            // 0..3
    const int ty = threadIdx.y;            // 0..7
    const int g  = threadIdx.z;            // 0..8 (dy) == warp id
    const int tid = tx + NTX * ty + NTX * TILE_Y * g;

    const int tileX = blockIdx.x * TILE_X;
    const int tileY = blockIdx.y * TILE_Y;
    const int b     = blockIdx.z;

    const float* Fb = F + (size_t)b * CHAN * HW;
    const float* Sb = S + (size_t)b * CHAN * HW;

    // ---------------- precompute load roles ----------------
    const float* s_ptr[S_ROLES];
    uint32_t     s_smem[S_ROLES];
    bool         s_pred[S_ROLES];
#pragma unroll
    for (int k = 0; k < S_ROLES; k++) {
        int v   = tid + k * NTHREADS;
        if (v >= S_VECS) v = 0;
        int ch  = v / (SROWS * SVEC);
        int rem = v - ch * (SROWS * SVEC);
        int row = rem / SVEC;
        int c4  = rem - row * SVEC;
        int gy  = tileY + row - MAXD;
        int gx  = tileX + c4 * 4 - MAXD;
        bool inb = (gy >= 0) && (gy < HH) && (gx >= 0) && (gx + 4 <= WW);
        s_pred[k] = inb;
        s_ptr[k]  = Sb + (size_t)ch * HW + (inb ? (gy * WW + gx) : 0);
        s_smem[k] = (uint32_t)__cvta_generic_to_shared(&sS[0][ch][row][c4 * 4]);
    }
    const float* f_ptr[F_ROLES];
    uint32_t     f_smem[F_ROLES];
#pragma unroll
    for (int k = 0; k < F_ROLES; k++) {
        int v   = tid + k * NTHREADS;
        if (v >= F_VECS) v = 0;
        int ch  = v >> 6;
        int rem = v & 63;
        int row = rem >> 3;
        int c4  = rem & 7;
        f_ptr[k]  = Fb + (size_t)ch * HW + (tileY + row) * WW + tileX + c4 * 4;
        f_smem[k] = (uint32_t)__cvta_generic_to_shared(&sF[0][ch][row][c4 * 4]);
    }

    auto issue = [&](int r) {
        uint32_t sOff = (r & 1) ? (uint32_t)S_BUF_BYTES : 0u;
        uint32_t fOff = (r & 1) ? (uint32_t)F_BUF_BYTES : 0u;
        size_t   cOff = (size_t)r * CH * HW;
#pragma unroll
        for (int k = 0; k < S_ROLES; k++) {
            if (k < S_ROLES - 1 || tid < (S_VECS - (S_ROLES - 1) * NTHREADS)) {
                cp_async16(s_smem[k] + sOff, s_ptr[k] + cOff, s_pred[k]);
            }
        }
#pragma unroll
        for (int k = 0; k < F_ROLES; k++) {
            if (k < F_ROLES - 1 || tid < (F_VECS - (F_ROLES - 1) * NTHREADS)) {
                cp_async16(f_smem[k] + fOff, f_ptr[k] + cOff, true);
            }
        }
        asm volatile("cp.async.commit_group;\n" ::: "memory");
    };

    // accumulators: 4 pixel-pairs x 9 dx, packed f32x2
    u64 A[4][WIN];
#pragma unroll
    for (int q = 0; q < 4; q++)
#pragma unroll
        for (int d = 0; d < WIN; d++) A[q][d] = 0ull;

    const int x0 = PX * tx;      // 0,8,16,24
    const int sy = ty + g;       // 0..15

    issue(0);

#pragma unroll 2
    for (int r = 0; r < NROUNDS; r++) {
        asm volatile("cp.async.wait_group 0;\n" ::: "memory");
        __syncthreads();
        if (r + 1 < NROUNDS) issue(r + 1);

        const int bb = r & 1;    // constant under unroll-2
#pragma unroll
        for (int ch = 0; ch < CH; ch++) {
            const float4* fr4 = (const float4*)&sF[bb][ch][ty][x0];
            float4 f0 = fr4[0];
            float4 f1 = fr4[1];
            const float4* wr4 = (const float4*)&sS[bb][ch][sy][x0];
            float4 w0 = wr4[0];
            float4 w1 = wr4[1];
            float4 w2 = wr4[2];
            float4 w3 = wr4[3];

            // f pairs: adjacent float4 members -> coalescible packs
            u64 fp[4] = { pk(f0.x, f0.y), pk(f0.z, f0.w),
                          pk(f1.x, f1.y), pk(f1.z, f1.w) };

            // even-start w pairs (within-float4, adjacent regs -> 0 MOVs)
            u64 we[8] = { pk(w0.x, w0.y), pk(w0.z, w0.w),
                          pk(w1.x, w1.y), pk(w1.z, w1.w),
                          pk(w2.x, w2.y), pk(w2.z, w2.w),
                          pk(w3.x, w3.y), pk(w3.z, w3.w) };

            // odd-start w pairs (cross-boundary -> 2 real MOVs each, min)
            u64 wo[7] = { pk(w0.y, w0.z), pk(w0.w, w1.x),
                          pk(w1.y, w1.z), pk(w1.w, w2.x),
                          pk(w2.y, w2.z), pk(w2.w, w3.x),
                          pk(w3.y, w3.z) };

            // A[q][d]: w pair starts at s = 2q+d.
#pragma unroll
            for (int q = 0; q < 4; q++) {
#pragma unroll
                for (int d = 0; d < WIN; d++) {
                    const int s = 2 * q + d;
                    if ((s & 1) == 0) ffma2(A[q][d], fp[q], we[s >> 1]);
                    else              ffma2(A[q][d], fp[q], wo[s >> 1]);
                }
            }
        }
    }

    // ---------------- store: scale by 1/C ----------------
    const float inv = 1.0f / (float)CHAN;
    const int y  = tileY + ty;
    const int gx = tileX + x0;
#pragma unroll
    for (int d = 0; d < WIN; d++) {
        int disp = g * WIN + d;
        float p0, p1, p2, p3, p4, p5, p6, p7;
        unpk(A[0][d], p0, p1);
        unpk(A[1][d], p2, p3);
        unpk(A[2][d], p4, p5);
        unpk(A[3][d], p6, p7);
        float4 v0 = { p0 * inv, p1 * inv, p2 * inv, p3 * inv };
        float4 v1 = { p4 * inv, p5 * inv, p6 * inv, p7 * inv };
        float* o = &out[((size_t)(b * NDISP + disp) * HH + y) * WW + gx];
        *(float4*)o       = v0;
        *(float4*)(o + 4) = v1;
    }
}

extern "C" void kernel_launch(void* const* d_in, const int* in_sizes, int n_in,
                              void* d_out, int out_size)
{
    const float* tensorFirst  = (const float*)d_in[0];
    const float* tensorSecond = (const float*)d_in[1];
    float* out = (float*)d_out;

    dim3 grid(WW / TILE_X, HH / TILE_Y, BATCH);   // 6 x 24 x 4 = 576
    dim3 block(NTX, TILE_Y, WIN);                 // 4 x 8 x 9 = 288
    corr_kernel<<<grid, block>>>(tensorFirst, tensorSecond, out);
}